// round 4
// baseline (speedup 1.0000x reference)
#include <cuda_runtime.h>
#include <math.h>
#include <stdint.h>

#define B_      2
#define S_      2048
#define HIDDEN_ 4096
#define HD_     128
#define HQ_     32
#define HKV_    8
#define WINDOW_ 1024
#define CAP_    50.0f
#define EPS_    1e-5f

#define M_ROWS  (B_ * S_)   // 4096

// ---------------- scratch (static device globals; no allocation) ----------------
__device__ float g_xn[(size_t)M_ROWS * HIDDEN_];
__device__ float g_q [(size_t)M_ROWS * HQ_  * HD_];
__device__ float g_k [(size_t)M_ROWS * HKV_ * HD_];
__device__ float g_v [(size_t)M_ROWS * HKV_ * HD_];
__device__ float g_ao[(size_t)M_ROWS * HQ_  * HD_];

// ---------------- RMSNorm: one block per row ----------------
__global__ void rmsnorm_kernel(const float* __restrict__ x,
                               const float* __restrict__ gamma,
                               float* __restrict__ xn) {
    int row = blockIdx.x;
    const float4* xr  = (const float4*)(x  + (size_t)row * HIDDEN_);
    float4*       xnr = (float4*)      (xn + (size_t)row * HIDDEN_);
    const float4* g4  = (const float4*)gamma;
    int t = threadIdx.x;

    float ss = 0.f;
    float4 vals[4];
#pragma unroll
    for (int i = 0; i < 4; i++) {
        float4 v = xr[t + i * 256];
        vals[i] = v;
        ss += v.x * v.x + v.y * v.y + v.z * v.z + v.w * v.w;
    }
    __shared__ float red[256];
    red[t] = ss;
    __syncthreads();
    for (int s = 128; s > 0; s >>= 1) {
        if (t < s) red[t] += red[t + s];
        __syncthreads();
    }
    float rms = rsqrtf(red[0] / (float)HIDDEN_ + EPS_);
#pragma unroll
    for (int i = 0; i < 4; i++) {
        float4 v = vals[i];
        float4 g = g4[t + i * 256];
        float4 o;
        o.x = v.x * rms * g.x;
        o.y = v.y * rms * g.y;
        o.z = v.z * rms * g.z;
        o.w = v.w * rms * g.w;
        xnr[t + i * 256] = o;
    }
}

// ---------------- TF32 tensor-core GEMM, double-buffered pipeline ----------------
// C[M,N] = A[M,K] @ B[K,N] (+resid). Block tile 128x128x16, 256 threads,
// warp grid 2(m) x 4(n), warp tile 64x32 via mma.m16n8k8 tf32.
#define TBM 128
#define TBN 128
#define TBK 16
#define APAD 20    // A smem row stride (floats): conflict-free frag loads
#define BPAD 132   // B smem row stride
#define ASZ (TBM * APAD)   // 2560
#define BSZ (TBK * BPAD)   // 2112

__device__ __forceinline__ uint32_t f2tf32(float f) {
    uint32_t r;
    asm("cvt.rna.tf32.f32 %0, %1;" : "=r"(r) : "f"(f));
    return r;
}

__global__ void __launch_bounds__(256, 2)
tf32_gemm_kernel(const float* __restrict__ A, const float* __restrict__ Bw,
                 const float* __restrict__ resid, float* __restrict__ C,
                 int N, int K) {
    __shared__ uint32_t As[2][ASZ];
    __shared__ uint32_t Bs[2][BSZ];

    int tid  = threadIdx.x;
    int warp = tid >> 5;
    int lane = tid & 31;
    int gid  = lane >> 2;       // 0..7
    int l4   = lane & 3;        // 0..3
    int wm = (warp & 1) * 64;   // warp m offset in tile
    int wn = (warp >> 1) * 32;  // warp n offset in tile

    size_t bm0 = (size_t)blockIdx.y * TBM;
    int    bn0 = blockIdx.x * TBN;

    const float* Ab = A  + bm0 * K;
    const float* Bb = Bw + bn0;

    // per-thread staging coordinates
    int arow = tid >> 1;            // 0..127  (2 threads per A row)
    int ac4  = (tid & 1) * 8;       // 0 or 8 (two float4 each)
    int brow = tid >> 4;            // 0..15
    int bc4  = (tid & 15) * 8;      // 0..120 (two float4 each)

    const float* ag = Ab + (size_t)arow * K + ac4;
    const float* bg = Bb + (size_t)brow * N + bc4;

    float acc[4][4][4];
#pragma unroll
    for (int mt = 0; mt < 4; mt++)
#pragma unroll
        for (int nt = 0; nt < 4; nt++)
#pragma unroll
            for (int r = 0; r < 4; r++) acc[mt][nt][r] = 0.f;

    int nk = K / TBK;

    float4 pa0, pa1, pb0, pb1;
    // prologue: load tile 0
    pa0 = *(const float4*)(ag);
    pa1 = *(const float4*)(ag + 4);
    pb0 = *(const float4*)(bg);
    pb1 = *(const float4*)(bg + 4);
    {
        uint32_t* d = &As[0][arow * APAD + ac4];
        d[0] = f2tf32(pa0.x); d[1] = f2tf32(pa0.y);
        d[2] = f2tf32(pa0.z); d[3] = f2tf32(pa0.w);
        d[4] = f2tf32(pa1.x); d[5] = f2tf32(pa1.y);
        d[6] = f2tf32(pa1.z); d[7] = f2tf32(pa1.w);
        uint32_t* e = &Bs[0][brow * BPAD + bc4];
        e[0] = f2tf32(pb0.x); e[1] = f2tf32(pb0.y);
        e[2] = f2tf32(pb0.z); e[3] = f2tf32(pb0.w);
        e[4] = f2tf32(pb1.x); e[5] = f2tf32(pb1.y);
        e[6] = f2tf32(pb1.z); e[7] = f2tf32(pb1.w);
    }
    __syncthreads();

    for (int kt = 0; kt < nk; kt++) {
        int nxt = kt + 1;
        // issue next tile's loads early (overlap with MMA below)
        if (nxt < nk) {
            const float* agn = ag + nxt * TBK;
            const float* bgn = bg + (size_t)nxt * TBK * N;
            pa0 = *(const float4*)(agn);
            pa1 = *(const float4*)(agn + 4);
            pb0 = *(const float4*)(bgn);
            pb1 = *(const float4*)(bgn + 4);
        }

        const uint32_t* Ac = As[kt & 1];
        const uint32_t* Bc = Bs[kt & 1];
#pragma unroll
        for (int kk = 0; kk < TBK; kk += 8) {
            uint32_t a[4][4], b[4][2];
#pragma unroll
            for (int mt = 0; mt < 4; mt++) {
                int ab = (wm + mt * 16 + gid) * APAD + kk + l4;
                a[mt][0] = Ac[ab];
                a[mt][1] = Ac[ab + 8 * APAD];
                a[mt][2] = Ac[ab + 4];
                a[mt][3] = Ac[ab + 8 * APAD + 4];
            }
#pragma unroll
            for (int nt = 0; nt < 4; nt++) {
                int bb = (kk + l4) * BPAD + wn + nt * 8 + gid;
                b[nt][0] = Bc[bb];
                b[nt][1] = Bc[bb + 4 * BPAD];
            }
#pragma unroll
            for (int mt = 0; mt < 4; mt++)
#pragma unroll
                for (int nt = 0; nt < 4; nt++) {
                    asm volatile(
                        "mma.sync.aligned.m16n8k8.row.col.f32.tf32.tf32.f32 "
                        "{%0,%1,%2,%3}, {%4,%5,%6,%7}, {%8,%9}, {%0,%1,%2,%3};"
                        : "+f"(acc[mt][nt][0]), "+f"(acc[mt][nt][1]),
                          "+f"(acc[mt][nt][2]), "+f"(acc[mt][nt][3])
                        : "r"(a[mt][0]), "r"(a[mt][1]), "r"(a[mt][2]), "r"(a[mt][3]),
                          "r"(b[nt][0]), "r"(b[nt][1]));
                }
        }

        if (nxt < nk) {
            uint32_t* d = &As[nxt & 1][arow * APAD + ac4];
            d[0] = f2tf32(pa0.x); d[1] = f2tf32(pa0.y);
            d[2] = f2tf32(pa0.z); d[3] = f2tf32(pa0.w);
            d[4] = f2tf32(pa1.x); d[5] = f2tf32(pa1.y);
            d[6] = f2tf32(pa1.z); d[7] = f2tf32(pa1.w);
            uint32_t* e = &Bs[nxt & 1][brow * BPAD + bc4];
            e[0] = f2tf32(pb0.x); e[1] = f2tf32(pb0.y);
            e[2] = f2tf32(pb0.z); e[3] = f2tf32(pb0.w);
            e[4] = f2tf32(pb1.x); e[5] = f2tf32(pb1.y);
            e[6] = f2tf32(pb1.z); e[7] = f2tf32(pb1.w);
        }
        __syncthreads();
    }

    // epilogue
#pragma unroll
    for (int mt = 0; mt < 4; mt++) {
#pragma unroll
        for (int nt = 0; nt < 4; nt++) {
            int row = wm + mt * 16 + gid;
            int col = wn + nt * 8 + l4 * 2;
            size_t g0 = (bm0 + row) * N + bn0 + col;
            size_t g1 = g0 + (size_t)8 * N;
            float2 v0 = make_float2(acc[mt][nt][0], acc[mt][nt][1]);
            float2 v1 = make_float2(acc[mt][nt][2], acc[mt][nt][3]);
            if (resid) {
                float2 r0 = *(const float2*)(resid + g0);
                float2 r1 = *(const float2*)(resid + g1);
                v0.x += r0.x; v0.y += r0.y;
                v1.x += r1.x; v1.y += r1.y;
            }
            *(float2*)(C + g0) = v0;
            *(float2*)(C + g1) = v1;
        }
    }
}

// ---------------- RoPE (in place), t shaped [B,S,n_heads,HD] ----------------
__global__ void rope_kernel(float* __restrict__ t, int n_heads, int total) {
    int idx = blockIdx.x * blockDim.x + threadIdx.x;
    if (idx >= total) return;
    int d   = idx & 63;
    int h   = (idx >> 6) % n_heads;
    int row = idx / (64 * n_heads);     // b*S + s
    int s   = row % S_;

    float inv = expf(-((float)(2 * d) / (float)HD_) * logf(10000.0f));
    float ang = (float)s * inv;
    float c, sn;
    sincosf(ang, &sn, &c);

    float* base = t + ((size_t)row * n_heads + h) * HD_;
    float v1 = base[d];
    float v2 = base[d + 64];
    base[d]      = v1 * c - v2 * sn;
    base[d + 64] = v2 * c + v1 * sn;
}

// ---------------- windowed causal attention, lane-per-key flash style ----------------
#define NW    16
#define AQW   4
#define AQB   (NW * AQW)     // 64
#define AT    32
#define KPAD  132            // 128 + 4 floats pad

#define ATTN_SMEM_FLOATS (2 * AT * KPAD + AQB * HD_ + NW * AT * 8)
#define ATTN_SMEM_BYTES  (ATTN_SMEM_FLOATS * 4)   // 82944

__global__ void __launch_bounds__(512, 2)
attn_kernel(const float* __restrict__ q, const float* __restrict__ k,
            const float* __restrict__ v, float* __restrict__ o) {
    extern __shared__ float sm[];
    float* Ks = sm;                       // [AT][KPAD]
    float* Vs = Ks + AT * KPAD;           // [AT][KPAD]
    float* Qs = Vs + AT * KPAD;           // [AQB][HD_]
    float* Ps = Qs + AQB * HD_;           // [NW][AT][8]

    int tid  = threadIdx.x;
    int warp = tid >> 5;
    int lane = tid & 31;
    int i0 = blockIdx.x * AQB;
    int h  = blockIdx.y;
    int b  = blockIdx.z;
    int g  = h >> 2;                      // HQ/HKV = 4
    int iw0 = i0 + warp * AQW;

    // stage Q tile: 64 rows x 128 floats
    {
        int r = tid >> 3;                 // 0..63
        int c = (tid & 7) * 16;           // 0..112
        const float4* src = (const float4*)(q + (((size_t)b * S_ + (i0 + r)) * HQ_ + h) * HD_ + c);
        float4* dst = (float4*)&Qs[r * HD_ + c];
#pragma unroll
        for (int u = 0; u < 4; u++) dst[u] = src[u];
    }

    float m[AQW], l[AQW];
    float4 acc[AQW];
#pragma unroll
    for (int qq = 0; qq < AQW; qq++) {
        m[qq] = -1e30f; l[qq] = 0.f;
        acc[qq] = make_float4(0.f, 0.f, 0.f, 0.f);
    }

    int jstart = max(0, i0 - (WINDOW_ - 1)) & ~(AT - 1);
    int jend   = i0 + AQB - 1;

    int lrow = tid >> 4;                  // 0..31
    int lcol = (tid & 15) * 8;            // 0..120

    const float scale = 0.08838834764831845f;   // 1/sqrt(128)
    float* pw = &Ps[warp * AT * 8];

    for (int t0 = jstart; t0 <= jend; t0 += AT) {
        {
            int j = t0 + lrow;
            const float* kp = k + (((size_t)b * S_ + j) * HKV_ + g) * HD_ + lcol;
            const float* vp = v + (((size_t)b * S_ + j) * HKV_ + g) * HD_ + lcol;
            *(float4*)&Ks[lrow * KPAD + lcol]     = ((const float4*)kp)[0];
            *(float4*)&Ks[lrow * KPAD + lcol + 4] = ((const float4*)kp)[1];
            *(float4*)&Vs[lrow * KPAD + lcol]     = ((const float4*)vp)[0];
            *(float4*)&Vs[lrow * KPAD + lcol + 4] = ((const float4*)vp)[1];
        }
        __syncthreads();

        if (t0 <= iw0 + AQW - 1) {
            float s[AQW] = {0.f, 0.f, 0.f, 0.f};
            const float* krow = &Ks[lane * KPAD];
            const float* qbase = &Qs[warp * AQW * HD_];
#pragma unroll 8
            for (int d4 = 0; d4 < 32; d4++) {
                float4 kv = *(const float4*)(krow + d4 * 4);
#pragma unroll
                for (int qq = 0; qq < AQW; qq++) {
                    float4 qv = *(const float4*)(qbase + qq * HD_ + d4 * 4);
                    s[qq] += qv.x * kv.x + qv.y * kv.y + qv.z * kv.z + qv.w * kv.w;
                }
            }

            int j = t0 + lane;
#pragma unroll
            for (int qq = 0; qq < AQW; qq++) {
                int i = iw0 + qq;
                float sv = s[qq] * scale;
                float e2 = __expf(sv * (-2.0f / CAP_));
                sv = CAP_ * __fdividef(1.f - e2, 1.f + e2);
                bool valid = (j <= i) && (j > i - WINDOW_);
                sv = valid ? sv : -1e30f;

                float tm = sv;
#pragma unroll
                for (int off = 16; off > 0; off >>= 1)
                    tm = fmaxf(tm, __shfl_xor_sync(0xffffffffu, tm, off));
                float mn = fmaxf(m[qq], tm);
                float corr = __expf(m[qq] - mn);
                m[qq] = mn;
                float p = __expf(sv - mn);
                float psum = p;
#pragma unroll
                for (int off = 16; off > 0; off >>= 1)
                    psum += __shfl_xor_sync(0xffffffffu, psum, off);
                l[qq] = l[qq] * corr + psum;
                acc[qq].x *= corr; acc[qq].y *= corr;
                acc[qq].z *= corr; acc[qq].w *= corr;
                pw[lane * 8 + qq] = p;
            }
            __syncwarp();

#pragma unroll 4
            for (int jj = 0; jj < AT; jj++) {
                float4 pv = *(const float4*)(pw + jj * 8);
                float4 vv = *(const float4*)&Vs[jj * KPAD + lane * 4];
                acc[0].x += pv.x * vv.x; acc[0].y += pv.x * vv.y;
                acc[0].z += pv.x * vv.z; acc[0].w += pv.x * vv.w;
                acc[1].x += pv.y * vv.x; acc[1].y += pv.y * vv.y;
                acc[1].z += pv.y * vv.z; acc[1].w += pv.y * vv.w;
                acc[2].x += pv.z * vv.x; acc[2].y += pv.z * vv.y;
                acc[2].z += pv.z * vv.z; acc[2].w += pv.z * vv.w;
                acc[3].x += pv.w * vv.x; acc[3].y += pv.w * vv.y;
                acc[3].z += pv.w * vv.z; acc[3].w += pv.w * vv.w;
            }
        }
        __syncthreads();
    }

#pragma unroll
    for (int qq = 0; qq < AQW; qq++) {
        int i = iw0 + qq;
        float inv = 1.0f / l[qq];
        float4 o4 = make_float4(acc[qq].x * inv, acc[qq].y * inv,
                                acc[qq].z * inv, acc[qq].w * inv);
        *(float4*)(o + (((size_t)b * S_ + i) * HQ_ + h) * HD_ + lane * 4) = o4;
    }
}

// ---------------- launch ----------------
extern "C" void kernel_launch(void* const* d_in, const int* in_sizes, int n_in,
                              void* d_out, int out_size) {
    const float* x     = (const float*)d_in[0];
    const float* gamma = (const float*)d_in[1];
    const float* Wq    = (const float*)d_in[2];
    const float* Wk    = (const float*)d_in[3];
    const float* Wv    = (const float*)d_in[4];
    const float* Wo    = (const float*)d_in[5];
    float* out = (float*)d_out;

    float *xn, *qb, *kb, *vb, *ao;
    cudaGetSymbolAddress((void**)&xn, g_xn);
    cudaGetSymbolAddress((void**)&qb, g_q);
    cudaGetSymbolAddress((void**)&kb, g_k);
    cudaGetSymbolAddress((void**)&vb, g_v);
    cudaGetSymbolAddress((void**)&ao, g_ao);

    cudaFuncSetAttribute(attn_kernel,
                         cudaFuncAttributeMaxDynamicSharedMemorySize,
                         ATTN_SMEM_BYTES);

    // 1) RMSNorm
    rmsnorm_kernel<<<M_ROWS, 256>>>(x, gamma, xn);

    // 2) Q/K/V projections (tf32 tensor cores)
    dim3 gq(HQ_ * HD_ / TBN, M_ROWS / TBM);    // (32, 32)
    tf32_gemm_kernel<<<gq, 256>>>(xn, Wq, nullptr, qb, HQ_ * HD_, HIDDEN_);
    dim3 gk(HKV_ * HD_ / TBN, M_ROWS / TBM);   // (8, 32)
    tf32_gemm_kernel<<<gk, 256>>>(xn, Wk, nullptr, kb, HKV_ * HD_, HIDDEN_);
    tf32_gemm_kernel<<<gk, 256>>>(xn, Wv, nullptr, vb, HKV_ * HD_, HIDDEN_);

    // 3) RoPE on q and k
    int tot_q = B_ * S_ * HQ_ * (HD_ / 2);
    rope_kernel<<<(tot_q + 255) / 256, 256>>>(qb, HQ_, tot_q);
    int tot_k = B_ * S_ * HKV_ * (HD_ / 2);
    rope_kernel<<<(tot_k + 255) / 256, 256>>>(kb, HKV_, tot_k);

    // 4) attention
    dim3 ga(S_ / AQB, HQ_, B_);                // (32, 32, 2)
    attn_kernel<<<ga, 512, ATTN_SMEM_BYTES>>>(qb, kb, vb, ao);

    // 5) output projection + residual (tf32 tensor cores)
    dim3 go(HIDDEN_ / TBN, M_ROWS / TBM);      // (32, 32)
    tf32_gemm_kernel<<<go, 256>>>(ao, Wo, x, out, HIDDEN_, HQ_ * HD_);
}

// round 5
// speedup vs baseline: 1.4606x; 1.4606x over previous
#include <cuda_runtime.h>
#include <cuda_bf16.h>
#include <math.h>
#include <stdint.h>

#define B_      2
#define S_      2048
#define HIDDEN_ 4096
#define HD_     128
#define HQ_     32
#define HKV_    8
#define WINDOW_ 1024
#define CAP_    50.0f
#define EPS_    1e-5f

#define M_ROWS  (B_ * S_)   // 4096

// ---------------- scratch (static device globals; no allocation) ----------------
__device__ __nv_bfloat16 g_xn[(size_t)M_ROWS * HIDDEN_];
__device__ float g_q [(size_t)M_ROWS * HQ_  * HD_];
__device__ float g_k [(size_t)M_ROWS * HKV_ * HD_];
__device__ float g_v [(size_t)M_ROWS * HKV_ * HD_];
__device__ __nv_bfloat16 g_ao[(size_t)M_ROWS * HQ_ * HD_];
__device__ __nv_bfloat16 g_wq16[(size_t)HIDDEN_ * HQ_  * HD_];
__device__ __nv_bfloat16 g_wk16[(size_t)HIDDEN_ * HKV_ * HD_];
__device__ __nv_bfloat16 g_wv16[(size_t)HIDDEN_ * HKV_ * HD_];
__device__ __nv_bfloat16 g_wo16[(size_t)HQ_ * HD_ * HIDDEN_];

// ---------------- fp32 -> bf16 convert ----------------
__global__ void f2bf_kernel(const float4* __restrict__ src,
                            __nv_bfloat162* __restrict__ dst, int n4) {
    int i = blockIdx.x * blockDim.x + threadIdx.x;
    if (i >= n4) return;
    float4 v = src[i];
    dst[2 * i]     = __floats2bfloat162_rn(v.x, v.y);
    dst[2 * i + 1] = __floats2bfloat162_rn(v.z, v.w);
}

// ---------------- RMSNorm: one block per row, bf16 output ----------------
__global__ void rmsnorm_kernel(const float* __restrict__ x,
                               const float* __restrict__ gamma,
                               __nv_bfloat16* __restrict__ xn) {
    int row = blockIdx.x;
    const float4* xr = (const float4*)(x + (size_t)row * HIDDEN_);
    __nv_bfloat162* xnr = (__nv_bfloat162*)(xn + (size_t)row * HIDDEN_);
    const float4* g4 = (const float4*)gamma;
    int t = threadIdx.x;

    float ss = 0.f;
    float4 vals[4];
#pragma unroll
    for (int i = 0; i < 4; i++) {
        float4 v = xr[t + i * 256];
        vals[i] = v;
        ss += v.x * v.x + v.y * v.y + v.z * v.z + v.w * v.w;
    }
    __shared__ float red[256];
    red[t] = ss;
    __syncthreads();
    for (int s = 128; s > 0; s >>= 1) {
        if (t < s) red[t] += red[t + s];
        __syncthreads();
    }
    float rms = rsqrtf(red[0] / (float)HIDDEN_ + EPS_);
#pragma unroll
    for (int i = 0; i < 4; i++) {
        float4 v = vals[i];
        float4 g = g4[t + i * 256];
        int c = t + i * 256;
        xnr[2 * c]     = __floats2bfloat162_rn(v.x * rms * g.x, v.y * rms * g.y);
        xnr[2 * c + 1] = __floats2bfloat162_rn(v.z * rms * g.z, v.w * rms * g.w);
    }
}

// ---------------- BF16 tensor-core GEMM ----------------
// C[M,N] = A[M,K] @ B[K,N] (+resid fp32). Block 128x128x32, 256 threads,
// warps 2(m) x 4(n), warp tile 64x32, mma.m16n8k16 bf16 / fp32 accum.
#define TBM 128
#define TBN 128
#define TBK 32
#define AP  20    // A smem row stride in uint32 units (80B) - conflict-free frags
#define BPB 136   // B smem row stride in bf16 (272B) - conflict-free ldmatrix

__global__ void __launch_bounds__(256)
bf16_gemm_kernel(const __nv_bfloat16* __restrict__ A,
                 const __nv_bfloat16* __restrict__ Bw,
                 const float* __restrict__ resid, float* __restrict__ C,
                 int N, int K) {
    __shared__ uint32_t As[TBM * AP];              // 10240 B
    __shared__ __nv_bfloat16 Bs[TBK * BPB];        // 8704 B

    int tid  = threadIdx.x;
    int warp = tid >> 5;
    int lane = tid & 31;
    int gid  = lane >> 2;
    int l4   = lane & 3;
    int wm = (warp & 1) * 64;
    int wn = (warp >> 1) * 32;

    size_t bm0 = (size_t)blockIdx.y * TBM;
    int    bn0 = blockIdx.x * TBN;

    // staging coords
    int arow = tid >> 1;
    int aco  = (tid & 1) * 16;                     // bf16 col
    int brow = 2 * (tid >> 4) + (tid & 1);
    int bco  = ((tid >> 1) & 7) * 16;              // bf16 col

    const __nv_bfloat16* ag = A + (bm0 + arow) * K + aco;
    const __nv_bfloat16* bg = Bw + (size_t)brow * N + bn0 + bco;
    uint4* asd = (uint4*)&As[arow * AP + (aco >> 1)];
    uint4* bsd = (uint4*)&Bs[brow * BPB + bco];

    // ldmatrix lane addresses (B): matrix lmat, row lrow
    uint32_t bsb = (uint32_t)__cvta_generic_to_shared(Bs);
    int lmat = lane >> 3;
    int lrow = lane & 7;
    uint32_t baddr[2];
#pragma unroll
    for (int p = 0; p < 2; p++)
        baddr[p] = bsb + 2u * (((lmat & 1) * 8 + lrow) * BPB
                               + wn + p * 16 + (lmat >> 1) * 8);

    float acc[4][4][4];
#pragma unroll
    for (int mt = 0; mt < 4; mt++)
#pragma unroll
        for (int nt = 0; nt < 4; nt++)
#pragma unroll
            for (int r = 0; r < 4; r++) acc[mt][nt][r] = 0.f;

    int nk = K / TBK;
    for (int kt = 0; kt < nk; kt++) {
        // stage A (32B/thread) and B (32B/thread)
        uint4 av0 = *(const uint4*)(ag);
        uint4 av1 = *(const uint4*)(ag + 8);
        uint4 bv0 = *(const uint4*)(bg);
        uint4 bv1 = *(const uint4*)(bg + 8);
        ag += TBK;
        bg += (size_t)TBK * N;
        asd[0] = av0; asd[1] = av1;
        bsd[0] = bv0; bsd[1] = bv1;
        __syncthreads();

#pragma unroll
        for (int kk = 0; kk < 2; kk++) {
            uint32_t a[4][4];
#pragma unroll
            for (int mt = 0; mt < 4; mt++) {
                int base = (wm + mt * 16 + gid) * AP + kk * 8 + l4;
                a[mt][0] = As[base];
                a[mt][1] = As[base + 8 * AP];
                a[mt][2] = As[base + 4];
                a[mt][3] = As[base + 8 * AP + 4];
            }
            uint32_t bf[2][4];
#pragma unroll
            for (int p = 0; p < 2; p++) {
                uint32_t ad = baddr[p] + kk * 16 * BPB * 2;
                asm volatile(
                    "ldmatrix.sync.aligned.m8n8.x4.trans.shared.b16 "
                    "{%0,%1,%2,%3}, [%4];"
                    : "=r"(bf[p][0]), "=r"(bf[p][1]),
                      "=r"(bf[p][2]), "=r"(bf[p][3])
                    : "r"(ad));
            }
#pragma unroll
            for (int mt = 0; mt < 4; mt++)
#pragma unroll
                for (int nt = 0; nt < 4; nt++) {
                    uint32_t b0 = bf[nt >> 1][(nt & 1) * 2];
                    uint32_t b1 = bf[nt >> 1][(nt & 1) * 2 + 1];
                    asm volatile(
                        "mma.sync.aligned.m16n8k16.row.col.f32.bf16.bf16.f32 "
                        "{%0,%1,%2,%3}, {%4,%5,%6,%7}, {%8,%9}, {%0,%1,%2,%3};"
                        : "+f"(acc[mt][nt][0]), "+f"(acc[mt][nt][1]),
                          "+f"(acc[mt][nt][2]), "+f"(acc[mt][nt][3])
                        : "r"(a[mt][0]), "r"(a[mt][1]),
                          "r"(a[mt][2]), "r"(a[mt][3]),
                          "r"(b0), "r"(b1));
                }
        }
        __syncthreads();
    }

    // epilogue
#pragma unroll
    for (int mt = 0; mt < 4; mt++) {
#pragma unroll
        for (int nt = 0; nt < 4; nt++) {
            int row = wm + mt * 16 + gid;
            int col = wn + nt * 8 + l4 * 2;
            size_t g0 = (bm0 + row) * N + bn0 + col;
            size_t g1 = g0 + (size_t)8 * N;
            float2 v0 = make_float2(acc[mt][nt][0], acc[mt][nt][1]);
            float2 v1 = make_float2(acc[mt][nt][2], acc[mt][nt][3]);
            if (resid) {
                float2 r0 = *(const float2*)(resid + g0);
                float2 r1 = *(const float2*)(resid + g1);
                v0.x += r0.x; v0.y += r0.y;
                v1.x += r1.x; v1.y += r1.y;
            }
            *(float2*)(C + g0) = v0;
            *(float2*)(C + g1) = v1;
        }
    }
}

// ---------------- RoPE (in place), t shaped [B,S,n_heads,HD] ----------------
__global__ void rope_kernel(float* __restrict__ t, int n_heads, int total) {
    int idx = blockIdx.x * blockDim.x + threadIdx.x;
    if (idx >= total) return;
    int d   = idx & 63;
    int h   = (idx >> 6) % n_heads;
    int row = idx / (64 * n_heads);     // b*S + s
    int s   = row % S_;

    float inv = expf(-((float)(2 * d) / (float)HD_) * logf(10000.0f));
    float ang = (float)s * inv;
    float c, sn;
    sincosf(ang, &sn, &c);

    float* base = t + ((size_t)row * n_heads + h) * HD_;
    float v1 = base[d];
    float v2 = base[d + 64];
    base[d]      = v1 * c - v2 * sn;
    base[d + 64] = v2 * c + v1 * sn;
}

// ---------------- windowed causal attention, lane-per-key flash style ----------------
#define NW    16
#define AQW   4
#define AQB   (NW * AQW)     // 64
#define AT    32
#define KPAD  132            // 128 + 4 floats pad

#define ATTN_SMEM_FLOATS (2 * AT * KPAD + AQB * HD_ + NW * AT * 8)
#define ATTN_SMEM_BYTES  (ATTN_SMEM_FLOATS * 4)   // 82944

__global__ void __launch_bounds__(512, 2)
attn_kernel(const float* __restrict__ q, const float* __restrict__ k,
            const float* __restrict__ v, __nv_bfloat16* __restrict__ o) {
    extern __shared__ float sm[];
    float* Ks = sm;                       // [AT][KPAD]
    float* Vs = Ks + AT * KPAD;           // [AT][KPAD]
    float* Qs = Vs + AT * KPAD;           // [AQB][HD_]
    float* Ps = Qs + AQB * HD_;           // [NW][AT][8]

    int tid  = threadIdx.x;
    int warp = tid >> 5;
    int lane = tid & 31;
    int i0 = blockIdx.x * AQB;
    int h  = blockIdx.y;
    int b  = blockIdx.z;
    int g  = h >> 2;                      // HQ/HKV = 4
    int iw0 = i0 + warp * AQW;

    // stage Q tile: 64 rows x 128 floats
    {
        int r = tid >> 3;                 // 0..63
        int c = (tid & 7) * 16;           // 0..112
        const float4* src = (const float4*)(q + (((size_t)b * S_ + (i0 + r)) * HQ_ + h) * HD_ + c);
        float4* dst = (float4*)&Qs[r * HD_ + c];
#pragma unroll
        for (int u = 0; u < 4; u++) dst[u] = src[u];
    }

    float m[AQW], l[AQW];
    float4 acc[AQW];
#pragma unroll
    for (int qq = 0; qq < AQW; qq++) {
        m[qq] = -1e30f; l[qq] = 0.f;
        acc[qq] = make_float4(0.f, 0.f, 0.f, 0.f);
    }

    int jstart = max(0, i0 - (WINDOW_ - 1)) & ~(AT - 1);
    int jend   = i0 + AQB - 1;

    int lrow = tid >> 4;                  // 0..31
    int lcol = (tid & 15) * 8;            // 0..120

    const float scale = 0.08838834764831845f;   // 1/sqrt(128)
    float* pw = &Ps[warp * AT * 8];

    for (int t0 = jstart; t0 <= jend; t0 += AT) {
        {
            int j = t0 + lrow;
            const float* kp = k + (((size_t)b * S_ + j) * HKV_ + g) * HD_ + lcol;
            const float* vp = v + (((size_t)b * S_ + j) * HKV_ + g) * HD_ + lcol;
            *(float4*)&Ks[lrow * KPAD + lcol]     = ((const float4*)kp)[0];
            *(float4*)&Ks[lrow * KPAD + lcol + 4] = ((const float4*)kp)[1];
            *(float4*)&Vs[lrow * KPAD + lcol]     = ((const float4*)vp)[0];
            *(float4*)&Vs[lrow * KPAD + lcol + 4] = ((const float4*)vp)[1];
        }
        __syncthreads();

        if (t0 <= iw0 + AQW - 1) {
            float s[AQW] = {0.f, 0.f, 0.f, 0.f};
            const float* krow = &Ks[lane * KPAD];
            const float* qbase = &Qs[warp * AQW * HD_];
#pragma unroll 8
            for (int d4 = 0; d4 < 32; d4++) {
                float4 kv = *(const float4*)(krow + d4 * 4);
#pragma unroll
                for (int qq = 0; qq < AQW; qq++) {
                    float4 qv = *(const float4*)(qbase + qq * HD_ + d4 * 4);
                    s[qq] += qv.x * kv.x + qv.y * kv.y + qv.z * kv.z + qv.w * kv.w;
                }
            }

            int j = t0 + lane;
#pragma unroll
            for (int qq = 0; qq < AQW; qq++) {
                int i = iw0 + qq;
                float sv = s[qq] * scale;
                float e2 = __expf(sv * (-2.0f / CAP_));
                sv = CAP_ * __fdividef(1.f - e2, 1.f + e2);
                bool valid = (j <= i) && (j > i - WINDOW_);
                sv = valid ? sv : -1e30f;

                float tm = sv;
#pragma unroll
                for (int off = 16; off > 0; off >>= 1)
                    tm = fmaxf(tm, __shfl_xor_sync(0xffffffffu, tm, off));
                float mn = fmaxf(m[qq], tm);
                float corr = __expf(m[qq] - mn);
                m[qq] = mn;
                float p = __expf(sv - mn);
                float psum = p;
#pragma unroll
                for (int off = 16; off > 0; off >>= 1)
                    psum += __shfl_xor_sync(0xffffffffu, psum, off);
                l[qq] = l[qq] * corr + psum;
                acc[qq].x *= corr; acc[qq].y *= corr;
                acc[qq].z *= corr; acc[qq].w *= corr;
                pw[lane * 8 + qq] = p;
            }
            __syncwarp();

#pragma unroll 4
            for (int jj = 0; jj < AT; jj++) {
                float4 pv = *(const float4*)(pw + jj * 8);
                float4 vv = *(const float4*)&Vs[jj * KPAD + lane * 4];
                acc[0].x += pv.x * vv.x; acc[0].y += pv.x * vv.y;
                acc[0].z += pv.x * vv.z; acc[0].w += pv.x * vv.w;
                acc[1].x += pv.y * vv.x; acc[1].y += pv.y * vv.y;
                acc[1].z += pv.y * vv.z; acc[1].w += pv.y * vv.w;
                acc[2].x += pv.z * vv.x; acc[2].y += pv.z * vv.y;
                acc[2].z += pv.z * vv.z; acc[2].w += pv.z * vv.w;
                acc[3].x += pv.w * vv.x; acc[3].y += pv.w * vv.y;
                acc[3].z += pv.w * vv.z; acc[3].w += pv.w * vv.w;
            }
        }
        __syncthreads();
    }

#pragma unroll
    for (int qq = 0; qq < AQW; qq++) {
        int i = iw0 + qq;
        float inv = 1.0f / l[qq];
        __nv_bfloat162* op = (__nv_bfloat162*)(o + (((size_t)b * S_ + i) * HQ_ + h) * HD_ + lane * 4);
        op[0] = __floats2bfloat162_rn(acc[qq].x * inv, acc[qq].y * inv);
        op[1] = __floats2bfloat162_rn(acc[qq].z * inv, acc[qq].w * inv);
    }
}

// ---------------- launch ----------------
extern "C" void kernel_launch(void* const* d_in, const int* in_sizes, int n_in,
                              void* d_out, int out_size) {
    const float* x     = (const float*)d_in[0];
    const float* gamma = (const float*)d_in[1];
    const float* Wq    = (const float*)d_in[2];
    const float* Wk    = (const float*)d_in[3];
    const float* Wv    = (const float*)d_in[4];
    const float* Wo    = (const float*)d_in[5];
    float* out = (float*)d_out;

    __nv_bfloat16 *xn, *ao, *wq16, *wk16, *wv16, *wo16;
    float *qb, *kb, *vb;
    cudaGetSymbolAddress((void**)&xn, g_xn);
    cudaGetSymbolAddress((void**)&qb, g_q);
    cudaGetSymbolAddress((void**)&kb, g_k);
    cudaGetSymbolAddress((void**)&vb, g_v);
    cudaGetSymbolAddress((void**)&ao, g_ao);
    cudaGetSymbolAddress((void**)&wq16, g_wq16);
    cudaGetSymbolAddress((void**)&wk16, g_wk16);
    cudaGetSymbolAddress((void**)&wv16, g_wv16);
    cudaGetSymbolAddress((void**)&wo16, g_wo16);

    cudaFuncSetAttribute(attn_kernel,
                         cudaFuncAttributeMaxDynamicSharedMemorySize,
                         ATTN_SMEM_BYTES);

    // 0) weight conversion fp32 -> bf16
    {
        int n4q = HIDDEN_ * HQ_ * HD_ / 4;
        int n4k = HIDDEN_ * HKV_ * HD_ / 4;
        f2bf_kernel<<<(n4q + 255) / 256, 256>>>((const float4*)Wq, (__nv_bfloat162*)wq16, n4q);
        f2bf_kernel<<<(n4k + 255) / 256, 256>>>((const float4*)Wk, (__nv_bfloat162*)wk16, n4k);
        f2bf_kernel<<<(n4k + 255) / 256, 256>>>((const float4*)Wv, (__nv_bfloat162*)wv16, n4k);
        f2bf_kernel<<<(n4q + 255) / 256, 256>>>((const float4*)Wo, (__nv_bfloat162*)wo16, n4q);
    }

    // 1) RMSNorm (bf16 out)
    rmsnorm_kernel<<<M_ROWS, 256>>>(x, gamma, xn);

    // 2) Q/K/V projections (bf16 tensor cores, fp32 out)
    dim3 gq(HQ_ * HD_ / TBN, M_ROWS / TBM);    // (32, 32)
    bf16_gemm_kernel<<<gq, 256>>>(xn, wq16, nullptr, qb, HQ_ * HD_, HIDDEN_);
    dim3 gk(HKV_ * HD_ / TBN, M_ROWS / TBM);   // (8, 32)
    bf16_gemm_kernel<<<gk, 256>>>(xn, wk16, nullptr, kb, HKV_ * HD_, HIDDEN_);
    bf16_gemm_kernel<<<gk, 256>>>(xn, wv16, nullptr, vb, HKV_ * HD_, HIDDEN_);

    // 3) RoPE on q and k (fp32)
    int tot_q = B_ * S_ * HQ_ * (HD_ / 2);
    rope_kernel<<<(tot_q + 255) / 256, 256>>>(qb, HQ_, tot_q);
    int tot_k = B_ * S_ * HKV_ * (HD_ / 2);
    rope_kernel<<<(tot_k + 255) / 256, 256>>>(kb, HKV_, tot_k);

    // 4) attention (fp32 math, bf16 out for Wo GEMM)
    dim3 ga(S_ / AQB, HQ_, B_);                // (32, 32, 2)
    attn_kernel<<<ga, 512, ATTN_SMEM_BYTES>>>(qb, kb, vb, ao);

    // 5) output projection + fp32 residual
    dim3 go(HIDDEN_ / TBN, M_ROWS / TBM);      // (32, 32)
    bf16_gemm_kernel<<<go, 256>>>(ao, wo16, x, out, HIDDEN_, HQ_ * HD_);
}

// round 6
// speedup vs baseline: 2.7890x; 1.9094x over previous
#include <cuda_runtime.h>
#include <cuda_bf16.h>
#include <math.h>
#include <stdint.h>

#define B_      2
#define S_      2048
#define HIDDEN_ 4096
#define HD_     128
#define HQ_     32
#define HKV_    8
#define WINDOW_ 1024
#define CAP_    50.0f
#define EPS_    1e-5f

#define M_ROWS  (B_ * S_)   // 4096

// ---------------- scratch (static device globals; no allocation) ----------------
__device__ __nv_bfloat16 g_xn[(size_t)M_ROWS * HIDDEN_];
__device__ float g_q [(size_t)M_ROWS * HQ_  * HD_];
__device__ float g_k [(size_t)M_ROWS * HKV_ * HD_];
__device__ float g_v [(size_t)M_ROWS * HKV_ * HD_];
__device__ __nv_bfloat16 g_q16[(size_t)M_ROWS * HQ_  * HD_];
__device__ __nv_bfloat16 g_k16[(size_t)M_ROWS * HKV_ * HD_];
__device__ __nv_bfloat16 g_v16[(size_t)M_ROWS * HKV_ * HD_];
__device__ __nv_bfloat16 g_ao[(size_t)M_ROWS * HQ_ * HD_];
__device__ __nv_bfloat16 g_wq16[(size_t)HIDDEN_ * HQ_  * HD_];
__device__ __nv_bfloat16 g_wk16[(size_t)HIDDEN_ * HKV_ * HD_];
__device__ __nv_bfloat16 g_wv16[(size_t)HIDDEN_ * HKV_ * HD_];
__device__ __nv_bfloat16 g_wo16[(size_t)HQ_ * HD_ * HIDDEN_];

// ---------------- helpers ----------------
__device__ __forceinline__ uint32_t packbf(float a, float b) {
    __nv_bfloat162 t = __floats2bfloat162_rn(a, b);
    return *reinterpret_cast<uint32_t*>(&t);
}
__device__ __forceinline__ uint32_t smem_u32(const void* p) {
    return (uint32_t)__cvta_generic_to_shared(p);
}

// ---------------- fp32 -> bf16 convert ----------------
__global__ void f2bf_kernel(const float4* __restrict__ src,
                            __nv_bfloat162* __restrict__ dst, int n4) {
    int i = blockIdx.x * blockDim.x + threadIdx.x;
    if (i >= n4) return;
    float4 v = src[i];
    dst[2 * i]     = __floats2bfloat162_rn(v.x, v.y);
    dst[2 * i + 1] = __floats2bfloat162_rn(v.z, v.w);
}

// ---------------- RMSNorm: one block per row, bf16 output ----------------
__global__ void rmsnorm_kernel(const float* __restrict__ x,
                               const float* __restrict__ gamma,
                               __nv_bfloat16* __restrict__ xn) {
    int row = blockIdx.x;
    const float4* xr = (const float4*)(x + (size_t)row * HIDDEN_);
    __nv_bfloat162* xnr = (__nv_bfloat162*)(xn + (size_t)row * HIDDEN_);
    const float4* g4 = (const float4*)gamma;
    int t = threadIdx.x;

    float ss = 0.f;
    float4 vals[4];
#pragma unroll
    for (int i = 0; i < 4; i++) {
        float4 v = xr[t + i * 256];
        vals[i] = v;
        ss += v.x * v.x + v.y * v.y + v.z * v.z + v.w * v.w;
    }
    __shared__ float red[256];
    red[t] = ss;
    __syncthreads();
    for (int s = 128; s > 0; s >>= 1) {
        if (t < s) red[t] += red[t + s];
        __syncthreads();
    }
    float rms = rsqrtf(red[0] / (float)HIDDEN_ + EPS_);
#pragma unroll
    for (int i = 0; i < 4; i++) {
        float4 v = vals[i];
        float4 g = g4[t + i * 256];
        int c = t + i * 256;
        xnr[2 * c]     = __floats2bfloat162_rn(v.x * rms * g.x, v.y * rms * g.y);
        xnr[2 * c + 1] = __floats2bfloat162_rn(v.z * rms * g.z, v.w * rms * g.w);
    }
}

// ---------------- BF16 tensor-core GEMM (unchanged from R5) ----------------
#define TBM 128
#define TBN 128
#define TBK 32
#define AP  20
#define BPB 136

__global__ void __launch_bounds__(256)
bf16_gemm_kernel(const __nv_bfloat16* __restrict__ A,
                 const __nv_bfloat16* __restrict__ Bw,
                 const float* __restrict__ resid, float* __restrict__ C,
                 int N, int K) {
    __shared__ uint32_t As[TBM * AP];
    __shared__ __nv_bfloat16 Bs[TBK * BPB];

    int tid  = threadIdx.x;
    int warp = tid >> 5;
    int lane = tid & 31;
    int gid  = lane >> 2;
    int l4   = lane & 3;
    int wm = (warp & 1) * 64;
    int wn = (warp >> 1) * 32;

    size_t bm0 = (size_t)blockIdx.y * TBM;
    int    bn0 = blockIdx.x * TBN;

    int arow = tid >> 1;
    int aco  = (tid & 1) * 16;
    int brow = 2 * (tid >> 4) + (tid & 1);
    int bco  = ((tid >> 1) & 7) * 16;

    const __nv_bfloat16* ag = A + (bm0 + arow) * K + aco;
    const __nv_bfloat16* bg = Bw + (size_t)brow * N + bn0 + bco;
    uint4* asd = (uint4*)&As[arow * AP + (aco >> 1)];
    uint4* bsd = (uint4*)&Bs[brow * BPB + bco];

    uint32_t bsb = smem_u32(Bs);
    int lmat = lane >> 3;
    int lrow = lane & 7;
    uint32_t baddr[2];
#pragma unroll
    for (int p = 0; p < 2; p++)
        baddr[p] = bsb + 2u * (((lmat & 1) * 8 + lrow) * BPB
                               + wn + p * 16 + (lmat >> 1) * 8);

    float acc[4][4][4];
#pragma unroll
    for (int mt = 0; mt < 4; mt++)
#pragma unroll
        for (int nt = 0; nt < 4; nt++)
#pragma unroll
            for (int r = 0; r < 4; r++) acc[mt][nt][r] = 0.f;

    int nk = K / TBK;
    for (int kt = 0; kt < nk; kt++) {
        uint4 av0 = *(const uint4*)(ag);
        uint4 av1 = *(const uint4*)(ag + 8);
        uint4 bv0 = *(const uint4*)(bg);
        uint4 bv1 = *(const uint4*)(bg + 8);
        ag += TBK;
        bg += (size_t)TBK * N;
        asd[0] = av0; asd[1] = av1;
        bsd[0] = bv0; bsd[1] = bv1;
        __syncthreads();

#pragma unroll
        for (int kk = 0; kk < 2; kk++) {
            uint32_t a[4][4];
#pragma unroll
            for (int mt = 0; mt < 4; mt++) {
                int base = (wm + mt * 16 + gid) * AP + kk * 8 + l4;
                a[mt][0] = As[base];
                a[mt][1] = As[base + 8 * AP];
                a[mt][2] = As[base + 4];
                a[mt][3] = As[base + 8 * AP + 4];
            }
            uint32_t bf[2][4];
#pragma unroll
            for (int p = 0; p < 2; p++) {
                uint32_t ad = baddr[p] + kk * 16 * BPB * 2;
                asm volatile(
                    "ldmatrix.sync.aligned.m8n8.x4.trans.shared.b16 "
                    "{%0,%1,%2,%3}, [%4];"
                    : "=r"(bf[p][0]), "=r"(bf[p][1]),
                      "=r"(bf[p][2]), "=r"(bf[p][3])
                    : "r"(ad));
            }
#pragma unroll
            for (int mt = 0; mt < 4; mt++)
#pragma unroll
                for (int nt = 0; nt < 4; nt++) {
                    uint32_t b0 = bf[nt >> 1][(nt & 1) * 2];
                    uint32_t b1 = bf[nt >> 1][(nt & 1) * 2 + 1];
                    asm volatile(
                        "mma.sync.aligned.m16n8k16.row.col.f32.bf16.bf16.f32 "
                        "{%0,%1,%2,%3}, {%4,%5,%6,%7}, {%8,%9}, {%0,%1,%2,%3};"
                        : "+f"(acc[mt][nt][0]), "+f"(acc[mt][nt][1]),
                          "+f"(acc[mt][nt][2]), "+f"(acc[mt][nt][3])
                        : "r"(a[mt][0]), "r"(a[mt][1]),
                          "r"(a[mt][2]), "r"(a[mt][3]),
                          "r"(b0), "r"(b1));
                }
        }
        __syncthreads();
    }

#pragma unroll
    for (int mt = 0; mt < 4; mt++) {
#pragma unroll
        for (int nt = 0; nt < 4; nt++) {
            int row = wm + mt * 16 + gid;
            int col = wn + nt * 8 + l4 * 2;
            size_t g0 = (bm0 + row) * N + bn0 + col;
            size_t g1 = g0 + (size_t)8 * N;
            float2 v0 = make_float2(acc[mt][nt][0], acc[mt][nt][1]);
            float2 v1 = make_float2(acc[mt][nt][2], acc[mt][nt][3]);
            if (resid) {
                float2 r0 = *(const float2*)(resid + g0);
                float2 r1 = *(const float2*)(resid + g1);
                v0.x += r0.x; v0.y += r0.y;
                v1.x += r1.x; v1.y += r1.y;
            }
            *(float2*)(C + g0) = v0;
            *(float2*)(C + g1) = v1;
        }
    }
}

// ---------------- RoPE fp32 -> bf16 ----------------
__global__ void rope_bf16_kernel(const float* __restrict__ src,
                                 __nv_bfloat16* __restrict__ dst,
                                 int n_heads, int total) {
    int idx = blockIdx.x * blockDim.x + threadIdx.x;
    if (idx >= total) return;
    int d   = idx & 63;
    int h   = (idx >> 6) % n_heads;
    int row = idx / (64 * n_heads);
    int s   = row % S_;

    float inv = expf(-((float)(2 * d) / (float)HD_) * logf(10000.0f));
    float ang = (float)s * inv;
    float c, sn;
    sincosf(ang, &sn, &c);

    size_t base = ((size_t)row * n_heads + h) * HD_;
    float v1 = src[base + d];
    float v2 = src[base + d + 64];
    dst[base + d]      = __float2bfloat16(v1 * c - v2 * sn);
    dst[base + d + 64] = __float2bfloat16(v2 * c + v1 * sn);
}

// ---------------- tensor-core flash attention ----------------
// Block: 128 threads (4 warps), 64 queries of one (b,h). Warp = 16 query rows.
// K tiles of 32 keys. bf16 mma m16n8k16, fp32 softmax/accum.
#define QT 64
#define KT 32
#define SPAD 136

__global__ void __launch_bounds__(128)
attn_mma_kernel(const __nv_bfloat16* __restrict__ q,
                const __nv_bfloat16* __restrict__ k,
                const __nv_bfloat16* __restrict__ v,
                __nv_bfloat16* __restrict__ o) {
    __shared__ __nv_bfloat16 Qs[QT * SPAD];
    __shared__ __nv_bfloat16 Ks[KT * SPAD];
    __shared__ __nv_bfloat16 Vs[KT * SPAD];

    int tid  = threadIdx.x;
    int warp = tid >> 5;
    int lane = tid & 31;
    int gid  = lane >> 2;
    int l4   = lane & 3;
    int lrow = lane & 7;
    int lmat = lane >> 3;
    int i0 = blockIdx.x * QT;
    int h  = blockIdx.y;
    int b  = blockIdx.z;
    int g  = h >> 2;
    int wrow = warp * 16;

    // stage Q tile 64x128 bf16
    {
        int r = tid >> 1;
        int c = (tid & 1) * 64;
        const uint4* src = (const uint4*)(q + (((size_t)b * S_ + i0 + r) * HQ_ + h) * HD_ + c);
        uint4* dst = (uint4*)&Qs[r * SPAD + c];
#pragma unroll
        for (int u = 0; u < 8; u++) dst[u] = src[u];
    }
    __syncthreads();

    // Q fragments: 8 k-steps x 4 regs (kept resident)
    uint32_t qsb = smem_u32(Qs);
    uint32_t a_q[8][4];
#pragma unroll
    for (int ks = 0; ks < 8; ks++) {
        int mrow = wrow + (lmat & 1) * 8 + lrow;
        int mcol = ks * 16 + (lmat >> 1) * 8;
        uint32_t ad = qsb + 2u * (mrow * SPAD + mcol);
        asm volatile("ldmatrix.sync.aligned.m8n8.x4.shared.b16 {%0,%1,%2,%3}, [%4];"
                     : "=r"(a_q[ks][0]), "=r"(a_q[ks][1]),
                       "=r"(a_q[ks][2]), "=r"(a_q[ks][3]) : "r"(ad));
    }

    uint32_t ksb = smem_u32(Ks);
    uint32_t vsb = smem_u32(Vs);

    float m0 = -1e30f, m1 = -1e30f, l0 = 0.f, l1 = 0.f;
    float oa[16][4];
#pragma unroll
    for (int nt = 0; nt < 16; nt++)
#pragma unroll
        for (int r = 0; r < 4; r++) oa[nt][r] = 0.f;

    int irow0 = i0 + wrow + gid;
    int irow1 = irow0 + 8;
    int iwmax = i0 + wrow + 15;     // largest row this warp owns
    int iwmin = i0 + wrow;          // smallest

    int jstart = max(0, i0 - (WINDOW_ - 1)) & ~(KT - 1);
    const float scale = 0.08838834764831845f;

    const __nv_bfloat16* kb = k + (size_t)b * S_ * HKV_ * HD_ + g * HD_;
    const __nv_bfloat16* vb = v + (size_t)b * S_ * HKV_ * HD_ + g * HD_;

    for (int t0 = jstart; t0 <= i0 + QT - 1; t0 += KT) {
        // stage K/V tile 32x128 each
        {
            int r = tid >> 2;
            int c = (tid & 3) * 32;
            size_t off = (size_t)(t0 + r) * (HKV_ * HD_) + c;
            const uint4* srk = (const uint4*)(kb + off);
            const uint4* srv = (const uint4*)(vb + off);
            uint4* dk = (uint4*)&Ks[r * SPAD + c];
            uint4* dv = (uint4*)&Vs[r * SPAD + c];
#pragma unroll
            for (int u = 0; u < 4; u++) { dk[u] = srk[u]; dv[u] = srv[u]; }
        }
        __syncthreads();

        // warp-level skip: tile entirely after this warp's rows, or entirely
        // before every row's window
        bool live = (t0 <= iwmax) && (t0 + KT - 1 > iwmin - WINDOW_);
        if (live) {
            // ---- S = Q K^T (64x32 per warp: 16 rows) ----
            float s[4][4];
#pragma unroll
            for (int nt = 0; nt < 4; nt++)
#pragma unroll
                for (int r = 0; r < 4; r++) s[nt][r] = 0.f;

#pragma unroll
            for (int ks = 0; ks < 8; ks++) {
                uint32_t b0[4], b1[4];
#pragma unroll
                for (int p = 0; p < 2; p++) {
                    int mrow = p * 16 + (lmat & 1) * 8 + lrow;
                    int mcol = ks * 16 + (lmat >> 1) * 8;
                    uint32_t ad = ksb + 2u * (mrow * SPAD + mcol);
                    uint32_t r0, r1, r2, r3;
                    asm volatile("ldmatrix.sync.aligned.m8n8.x4.shared.b16 {%0,%1,%2,%3}, [%4];"
                                 : "=r"(r0), "=r"(r1), "=r"(r2), "=r"(r3) : "r"(ad));
                    b0[2 * p] = r0; b0[2 * p + 1] = r1;
                    b1[2 * p] = r2; b1[2 * p + 1] = r3;
                }
#pragma unroll
                for (int nt = 0; nt < 4; nt++) {
                    asm volatile(
                        "mma.sync.aligned.m16n8k16.row.col.f32.bf16.bf16.f32 "
                        "{%0,%1,%2,%3}, {%4,%5,%6,%7}, {%8,%9}, {%0,%1,%2,%3};"
                        : "+f"(s[nt][0]), "+f"(s[nt][1]),
                          "+f"(s[nt][2]), "+f"(s[nt][3])
                        : "r"(a_q[ks][0]), "r"(a_q[ks][1]),
                          "r"(a_q[ks][2]), "r"(a_q[ks][3]),
                          "r"(b0[nt]), "r"(b1[nt]));
                }
            }

            // ---- scale + tanh cap + mask ----
            float mx0 = -1e30f, mx1 = -1e30f;
#pragma unroll
            for (int nt = 0; nt < 4; nt++) {
                int j0 = t0 + nt * 8 + 2 * l4;
#pragma unroll
                for (int e = 0; e < 4; e++) {
                    int jj = j0 + (e & 1);
                    int ii = (e < 2) ? irow0 : irow1;
                    float x = s[nt][e] * scale;
                    float e2 = __expf(x * (-2.0f / CAP_));
                    x = CAP_ * __fdividef(1.f - e2, 1.f + e2);
                    bool valid = (jj <= ii) && (jj > ii - WINDOW_);
                    x = valid ? x : -1e30f;
                    s[nt][e] = x;
                    if (e < 2) mx0 = fmaxf(mx0, x);
                    else       mx1 = fmaxf(mx1, x);
                }
            }
            mx0 = fmaxf(mx0, __shfl_xor_sync(0xffffffffu, mx0, 1));
            mx0 = fmaxf(mx0, __shfl_xor_sync(0xffffffffu, mx0, 2));
            mx1 = fmaxf(mx1, __shfl_xor_sync(0xffffffffu, mx1, 1));
            mx1 = fmaxf(mx1, __shfl_xor_sync(0xffffffffu, mx1, 2));

            float mn0 = fmaxf(m0, mx0), mn1 = fmaxf(m1, mx1);
            float c0 = __expf(m0 - mn0), c1 = __expf(m1 - mn1);
            m0 = mn0; m1 = mn1;

            float rs0 = 0.f, rs1 = 0.f;
#pragma unroll
            for (int nt = 0; nt < 4; nt++) {
#pragma unroll
                for (int e = 0; e < 4; e++) {
                    float p = __expf(s[nt][e] - ((e < 2) ? mn0 : mn1));
                    s[nt][e] = p;
                    if (e < 2) rs0 += p; else rs1 += p;
                }
            }
            rs0 += __shfl_xor_sync(0xffffffffu, rs0, 1);
            rs0 += __shfl_xor_sync(0xffffffffu, rs0, 2);
            rs1 += __shfl_xor_sync(0xffffffffu, rs1, 1);
            rs1 += __shfl_xor_sync(0xffffffffu, rs1, 2);
            l0 = l0 * c0 + rs0;
            l1 = l1 * c1 + rs1;

            // rescale O accumulator
#pragma unroll
            for (int nt = 0; nt < 16; nt++) {
                oa[nt][0] *= c0; oa[nt][1] *= c0;
                oa[nt][2] *= c1; oa[nt][3] *= c1;
            }

            // pack P into A fragments (2 k-steps of 16 keys)
            uint32_t ap[2][4];
#pragma unroll
            for (int kp = 0; kp < 2; kp++) {
                int nA = 2 * kp, nB = 2 * kp + 1;
                ap[kp][0] = packbf(s[nA][0], s[nA][1]);
                ap[kp][1] = packbf(s[nA][2], s[nA][3]);
                ap[kp][2] = packbf(s[nB][0], s[nB][1]);
                ap[kp][3] = packbf(s[nB][2], s[nB][3]);
            }

            // ---- O += P V ----
#pragma unroll
            for (int kp = 0; kp < 2; kp++) {
#pragma unroll
                for (int ndp = 0; ndp < 8; ndp++) {
                    int mrow = kp * 16 + (lmat & 1) * 8 + lrow;
                    int mcol = ndp * 16 + (lmat >> 1) * 8;
                    uint32_t ad = vsb + 2u * (mrow * SPAD + mcol);
                    uint32_t r0, r1, r2, r3;
                    asm volatile("ldmatrix.sync.aligned.m8n8.x4.trans.shared.b16 {%0,%1,%2,%3}, [%4];"
                                 : "=r"(r0), "=r"(r1), "=r"(r2), "=r"(r3) : "r"(ad));
                    asm volatile(
                        "mma.sync.aligned.m16n8k16.row.col.f32.bf16.bf16.f32 "
                        "{%0,%1,%2,%3}, {%4,%5,%6,%7}, {%8,%9}, {%0,%1,%2,%3};"
                        : "+f"(oa[2 * ndp][0]), "+f"(oa[2 * ndp][1]),
                          "+f"(oa[2 * ndp][2]), "+f"(oa[2 * ndp][3])
                        : "r"(ap[kp][0]), "r"(ap[kp][1]),
                          "r"(ap[kp][2]), "r"(ap[kp][3]),
                          "r"(r0), "r"(r1));
                    asm volatile(
                        "mma.sync.aligned.m16n8k16.row.col.f32.bf16.bf16.f32 "
                        "{%0,%1,%2,%3}, {%4,%5,%6,%7}, {%8,%9}, {%0,%1,%2,%3};"
                        : "+f"(oa[2 * ndp + 1][0]), "+f"(oa[2 * ndp + 1][1]),
                          "+f"(oa[2 * ndp + 1][2]), "+f"(oa[2 * ndp + 1][3])
                        : "r"(ap[kp][0]), "r"(ap[kp][1]),
                          "r"(ap[kp][2]), "r"(ap[kp][3]),
                          "r"(r2), "r"(r3));
                }
            }
        }
        __syncthreads();
    }

    // epilogue: normalize, write bf16
    float inv0 = 1.0f / l0;
    float inv1 = 1.0f / l1;
    __nv_bfloat16* ob0 = o + (((size_t)b * S_ + irow0) * HQ_ + h) * HD_;
    __nv_bfloat16* ob1 = o + (((size_t)b * S_ + irow1) * HQ_ + h) * HD_;
#pragma unroll
    for (int nt = 0; nt < 16; nt++) {
        int col = nt * 8 + 2 * l4;
        *(uint32_t*)(ob0 + col) = packbf(oa[nt][0] * inv0, oa[nt][1] * inv0);
        *(uint32_t*)(ob1 + col) = packbf(oa[nt][2] * inv1, oa[nt][3] * inv1);
    }
}

// ---------------- launch ----------------
extern "C" void kernel_launch(void* const* d_in, const int* in_sizes, int n_in,
                              void* d_out, int out_size) {
    const float* x     = (const float*)d_in[0];
    const float* gamma = (const float*)d_in[1];
    const float* Wq    = (const float*)d_in[2];
    const float* Wk    = (const float*)d_in[3];
    const float* Wv    = (const float*)d_in[4];
    const float* Wo    = (const float*)d_in[5];
    float* out = (float*)d_out;

    __nv_bfloat16 *xn, *ao, *wq16, *wk16, *wv16, *wo16, *q16, *k16, *v16;
    float *qb, *kb, *vb;
    cudaGetSymbolAddress((void**)&xn, g_xn);
    cudaGetSymbolAddress((void**)&qb, g_q);
    cudaGetSymbolAddress((void**)&kb, g_k);
    cudaGetSymbolAddress((void**)&vb, g_v);
    cudaGetSymbolAddress((void**)&q16, g_q16);
    cudaGetSymbolAddress((void**)&k16, g_k16);
    cudaGetSymbolAddress((void**)&v16, g_v16);
    cudaGetSymbolAddress((void**)&ao, g_ao);
    cudaGetSymbolAddress((void**)&wq16, g_wq16);
    cudaGetSymbolAddress((void**)&wk16, g_wk16);
    cudaGetSymbolAddress((void**)&wv16, g_wv16);
    cudaGetSymbolAddress((void**)&wo16, g_wo16);

    // 0) weight conversion fp32 -> bf16
    {
        int n4q = HIDDEN_ * HQ_ * HD_ / 4;
        int n4k = HIDDEN_ * HKV_ * HD_ / 4;
        f2bf_kernel<<<(n4q + 255) / 256, 256>>>((const float4*)Wq, (__nv_bfloat162*)wq16, n4q);
        f2bf_kernel<<<(n4k + 255) / 256, 256>>>((const float4*)Wk, (__nv_bfloat162*)wk16, n4k);
        f2bf_kernel<<<(n4k + 255) / 256, 256>>>((const float4*)Wv, (__nv_bfloat162*)wv16, n4k);
        f2bf_kernel<<<(n4q + 255) / 256, 256>>>((const float4*)Wo, (__nv_bfloat162*)wo16, n4q);
    }

    // 1) RMSNorm (bf16 out)
    rmsnorm_kernel<<<M_ROWS, 256>>>(x, gamma, xn);

    // 2) Q/K/V projections (bf16 tensor cores, fp32 out)
    dim3 gq(HQ_ * HD_ / TBN, M_ROWS / TBM);
    bf16_gemm_kernel<<<gq, 256>>>(xn, wq16, nullptr, qb, HQ_ * HD_, HIDDEN_);
    dim3 gk(HKV_ * HD_ / TBN, M_ROWS / TBM);
    bf16_gemm_kernel<<<gk, 256>>>(xn, wk16, nullptr, kb, HKV_ * HD_, HIDDEN_);
    bf16_gemm_kernel<<<gk, 256>>>(xn, wv16, nullptr, vb, HKV_ * HD_, HIDDEN_);

    // 3) RoPE fp32->bf16 on q,k; plain convert on v
    int tot_q = B_ * S_ * HQ_ * (HD_ / 2);
    rope_bf16_kernel<<<(tot_q + 255) / 256, 256>>>(qb, q16, HQ_, tot_q);
    int tot_k = B_ * S_ * HKV_ * (HD_ / 2);
    rope_bf16_kernel<<<(tot_k + 255) / 256, 256>>>(kb, k16, HKV_, tot_k);
    int n4v = M_ROWS * HKV_ * HD_ / 4;
    f2bf_kernel<<<(n4v + 255) / 256, 256>>>((const float4*)vb, (__nv_bfloat162*)v16, n4v);

    // 4) tensor-core flash attention
    dim3 ga(S_ / QT, HQ_, B_);                 // (32, 32, 2)
    attn_mma_kernel<<<ga, 128>>>(q16, k16, v16, ao);

    // 5) output projection + fp32 residual
    dim3 go(HIDDEN_ / TBN, M_ROWS / TBM);
    bf16_gemm_kernel<<<go, 256>>>(ao, wo16, x, out, HIDDEN_, HQ_ * HD_);
}

// round 7
// speedup vs baseline: 3.1372x; 1.1249x over previous
#include <cuda_runtime.h>
#include <cuda_bf16.h>
#include <math.h>
#include <stdint.h>

#define B_      2
#define S_      2048
#define HIDDEN_ 4096
#define HD_     128
#define HQ_     32
#define HKV_    8
#define WINDOW_ 1024
#define CAP_    50.0f
#define EPS_    1e-5f

#define M_ROWS  (B_ * S_)   // 4096

// ---------------- scratch (static device globals; no allocation) ----------------
__device__ __nv_bfloat16 g_xn[(size_t)M_ROWS * HIDDEN_];
__device__ __nv_bfloat16 g_q16[(size_t)M_ROWS * HQ_  * HD_];
__device__ __nv_bfloat16 g_k16[(size_t)M_ROWS * HKV_ * HD_];
__device__ __nv_bfloat16 g_v16[(size_t)M_ROWS * HKV_ * HD_];
__device__ __nv_bfloat16 g_ao[(size_t)M_ROWS * HQ_ * HD_];
__device__ __nv_bfloat16 g_wq16[(size_t)HIDDEN_ * HQ_  * HD_];
__device__ __nv_bfloat16 g_wk16[(size_t)HIDDEN_ * HKV_ * HD_];
__device__ __nv_bfloat16 g_wv16[(size_t)HIDDEN_ * HKV_ * HD_];
__device__ __nv_bfloat16 g_wo16[(size_t)HQ_ * HD_ * HIDDEN_];

// ---------------- helpers ----------------
__device__ __forceinline__ uint32_t packbf(float a, float b) {
    __nv_bfloat162 t = __floats2bfloat162_rn(a, b);
    return *reinterpret_cast<uint32_t*>(&t);
}
__device__ __forceinline__ uint32_t smem_u32(const void* p) {
    return (uint32_t)__cvta_generic_to_shared(p);
}
#define CP_ASYNC16(dst, src) \
    asm volatile("cp.async.cg.shared.global [%0], [%1], 16;" :: "r"(dst), "l"(src))
#define CP_COMMIT() asm volatile("cp.async.commit_group;")
#define CP_WAIT1()  asm volatile("cp.async.wait_group 1;")

// ---------------- fp32 -> bf16 convert ----------------
__global__ void f2bf_kernel(const float4* __restrict__ src,
                            __nv_bfloat162* __restrict__ dst, int n4) {
    int i = blockIdx.x * blockDim.x + threadIdx.x;
    if (i >= n4) return;
    float4 v = src[i];
    dst[2 * i]     = __floats2bfloat162_rn(v.x, v.y);
    dst[2 * i + 1] = __floats2bfloat162_rn(v.z, v.w);
}

// ---------------- RMSNorm: one block per row, bf16 output ----------------
__global__ void rmsnorm_kernel(const float* __restrict__ x,
                               const float* __restrict__ gamma,
                               __nv_bfloat16* __restrict__ xn) {
    int row = blockIdx.x;
    const float4* xr = (const float4*)(x + (size_t)row * HIDDEN_);
    __nv_bfloat162* xnr = (__nv_bfloat162*)(xn + (size_t)row * HIDDEN_);
    const float4* g4 = (const float4*)gamma;
    int t = threadIdx.x;

    float ss = 0.f;
    float4 vals[4];
#pragma unroll
    for (int i = 0; i < 4; i++) {
        float4 v = xr[t + i * 256];
        vals[i] = v;
        ss += v.x * v.x + v.y * v.y + v.z * v.z + v.w * v.w;
    }
    __shared__ float red[256];
    red[t] = ss;
    __syncthreads();
    for (int s = 128; s > 0; s >>= 1) {
        if (t < s) red[t] += red[t + s];
        __syncthreads();
    }
    float rms = rsqrtf(red[0] / (float)HIDDEN_ + EPS_);
#pragma unroll
    for (int i = 0; i < 4; i++) {
        float4 v = vals[i];
        float4 g = g4[t + i * 256];
        int c = t + i * 256;
        xnr[2 * c]     = __floats2bfloat162_rn(v.x * rms * g.x, v.y * rms * g.y);
        xnr[2 * c + 1] = __floats2bfloat162_rn(v.z * rms * g.z, v.w * rms * g.w);
    }
}

// ---------------- BF16 tensor-core GEMM, cp.async double-buffered ----------------
// C[M,N] = A[M,K] @ B[K,N]. OUTBF=0: fp32 out + fp32 resid. OUTBF=1: bf16 out.
#define TBM 128
#define TBN 128
#define TBK 32
#define AP  20          // A smem row stride in uint32 (80B)
#define BPB 136         // B smem row stride in bf16 (272B)
#define ASZ (TBM * AP)  // uint32 elems per A buffer
#define BSZ (TBK * BPB) // bf16 elems per B buffer

template<int OUTBF>
__global__ void __launch_bounds__(256)
bf16_gemm_kernel(const __nv_bfloat16* __restrict__ A,
                 const __nv_bfloat16* __restrict__ Bw,
                 const float* __restrict__ resid, void* __restrict__ Cout,
                 int N, int K) {
    __shared__ uint32_t As[2][ASZ];
    __shared__ __nv_bfloat16 Bs[2][BSZ];

    int tid  = threadIdx.x;
    int warp = tid >> 5;
    int lane = tid & 31;
    int gid  = lane >> 2;
    int l4   = lane & 3;
    int wm = (warp & 1) * 64;
    int wn = (warp >> 1) * 32;

    size_t bm0 = (size_t)blockIdx.y * TBM;
    int    bn0 = blockIdx.x * TBN;

    int arow = tid >> 1;
    int aco  = (tid & 1) * 16;              // bf16 col
    int brow = 2 * (tid >> 4) + (tid & 1);
    int bco  = ((tid >> 1) & 7) * 16;       // bf16 col

    const __nv_bfloat16* ag = A + (bm0 + arow) * K + aco;
    const __nv_bfloat16* bg = Bw + (size_t)brow * N + bn0 + bco;
    uint32_t a_dst0 = smem_u32(&As[0][arow * AP + (aco >> 1)]);
    uint32_t b_dst0 = smem_u32(&Bs[0][brow * BPB + bco]);

    uint32_t bsb = smem_u32(Bs);
    int lmat = lane >> 3;
    int lrow = lane & 7;
    uint32_t baddr[2];
#pragma unroll
    for (int p = 0; p < 2; p++)
        baddr[p] = bsb + 2u * (((lmat & 1) * 8 + lrow) * BPB
                               + wn + p * 16 + (lmat >> 1) * 8);

    float acc[4][4][4];
#pragma unroll
    for (int mt = 0; mt < 4; mt++)
#pragma unroll
        for (int nt = 0; nt < 4; nt++)
#pragma unroll
            for (int r = 0; r < 4; r++) acc[mt][nt][r] = 0.f;

    int nk = K / TBK;

    // prologue: stage tile 0 into buffer 0
    CP_ASYNC16(a_dst0, ag);
    CP_ASYNC16(a_dst0 + 16, ag + 8);
    CP_ASYNC16(b_dst0, bg);
    CP_ASYNC16(b_dst0 + 16, bg + 8);
    CP_COMMIT();

    for (int kt = 0; kt < nk; kt++) {
        int nxt = kt + 1;
        if (nxt < nk) {
            uint32_t boff = (nxt & 1);
            uint32_t ad = a_dst0 + boff * (ASZ * 4);
            uint32_t bd = b_dst0 + boff * (BSZ * 2);
            const __nv_bfloat16* agn = ag + nxt * TBK;
            const __nv_bfloat16* bgn = bg + (size_t)nxt * TBK * N;
            CP_ASYNC16(ad, agn);
            CP_ASYNC16(ad + 16, agn + 8);
            CP_ASYNC16(bd, bgn);
            CP_ASYNC16(bd + 16, bgn + 8);
        }
        CP_COMMIT();
        CP_WAIT1();
        __syncthreads();

        const uint32_t* Ac = As[kt & 1];
        uint32_t bufoff = (kt & 1) * (BSZ * 2);
#pragma unroll
        for (int kk = 0; kk < 2; kk++) {
            uint32_t a[4][4];
#pragma unroll
            for (int mt = 0; mt < 4; mt++) {
                int base = (wm + mt * 16 + gid) * AP + kk * 8 + l4;
                a[mt][0] = Ac[base];
                a[mt][1] = Ac[base + 8 * AP];
                a[mt][2] = Ac[base + 4];
                a[mt][3] = Ac[base + 8 * AP + 4];
            }
            uint32_t bf[2][4];
#pragma unroll
            for (int p = 0; p < 2; p++) {
                uint32_t ad = baddr[p] + bufoff + kk * 16 * BPB * 2;
                asm volatile(
                    "ldmatrix.sync.aligned.m8n8.x4.trans.shared.b16 "
                    "{%0,%1,%2,%3}, [%4];"
                    : "=r"(bf[p][0]), "=r"(bf[p][1]),
                      "=r"(bf[p][2]), "=r"(bf[p][3])
                    : "r"(ad));
            }
#pragma unroll
            for (int mt = 0; mt < 4; mt++)
#pragma unroll
                for (int nt = 0; nt < 4; nt++) {
                    uint32_t b0 = bf[nt >> 1][(nt & 1) * 2];
                    uint32_t b1 = bf[nt >> 1][(nt & 1) * 2 + 1];
                    asm volatile(
                        "mma.sync.aligned.m16n8k16.row.col.f32.bf16.bf16.f32 "
                        "{%0,%1,%2,%3}, {%4,%5,%6,%7}, {%8,%9}, {%0,%1,%2,%3};"
                        : "+f"(acc[mt][nt][0]), "+f"(acc[mt][nt][1]),
                          "+f"(acc[mt][nt][2]), "+f"(acc[mt][nt][3])
                        : "r"(a[mt][0]), "r"(a[mt][1]),
                          "r"(a[mt][2]), "r"(a[mt][3]),
                          "r"(b0), "r"(b1));
                }
        }
        __syncthreads();
    }

    // epilogue
#pragma unroll
    for (int mt = 0; mt < 4; mt++) {
#pragma unroll
        for (int nt = 0; nt < 4; nt++) {
            int row = wm + mt * 16 + gid;
            int col = wn + nt * 8 + l4 * 2;
            size_t g0 = (bm0 + row) * N + bn0 + col;
            size_t g1 = g0 + (size_t)8 * N;
            if (OUTBF) {
                __nv_bfloat16* C16 = (__nv_bfloat16*)Cout;
                *(uint32_t*)(C16 + g0) = packbf(acc[mt][nt][0], acc[mt][nt][1]);
                *(uint32_t*)(C16 + g1) = packbf(acc[mt][nt][2], acc[mt][nt][3]);
            } else {
                float* C = (float*)Cout;
                float2 v0 = make_float2(acc[mt][nt][0], acc[mt][nt][1]);
                float2 v1 = make_float2(acc[mt][nt][2], acc[mt][nt][3]);
                float2 r0 = *(const float2*)(resid + g0);
                float2 r1 = *(const float2*)(resid + g1);
                v0.x += r0.x; v0.y += r0.y;
                v1.x += r1.x; v1.y += r1.y;
                *(float2*)(C + g0) = v0;
                *(float2*)(C + g1) = v1;
            }
        }
    }
}

// ---------------- RoPE in-place on bf16, t shaped [B,S,n_heads,HD] ----------------
__global__ void rope_bf16_inplace(__nv_bfloat16* __restrict__ t,
                                  int n_heads, int total) {
    int idx = blockIdx.x * blockDim.x + threadIdx.x;
    if (idx >= total) return;
    int d   = idx & 63;
    int h   = (idx >> 6) % n_heads;
    int row = idx / (64 * n_heads);
    int s   = row % S_;

    float inv = expf(-((float)(2 * d) / (float)HD_) * logf(10000.0f));
    float ang = (float)s * inv;
    float c, sn;
    sincosf(ang, &sn, &c);

    size_t base = ((size_t)row * n_heads + h) * HD_;
    float v1 = __bfloat162float(t[base + d]);
    float v2 = __bfloat162float(t[base + d + 64]);
    t[base + d]      = __float2bfloat16(v1 * c - v2 * sn);
    t[base + d + 64] = __float2bfloat16(v2 * c + v1 * sn);
}

// ---------------- tensor-core flash attention, cp.async K/V double buffer ----------
#define QT 64
#define KT 32
#define SPAD 136
// dynamic smem: Qs[QT*SPAD] + Ks[2][KT*SPAD] + Vs[2][KT*SPAD]  (bf16)
#define ATTN_SMEM_BYTES ((QT * SPAD + 4 * KT * SPAD) * 2)   // 52224

__global__ void __launch_bounds__(128)
attn_mma_kernel(const __nv_bfloat16* __restrict__ q,
                const __nv_bfloat16* __restrict__ k,
                const __nv_bfloat16* __restrict__ v,
                __nv_bfloat16* __restrict__ o) {
    extern __shared__ __nv_bfloat16 smb[];
    __nv_bfloat16* Qs = smb;
    __nv_bfloat16* Ks = Qs + QT * SPAD;          // 2 buffers
    __nv_bfloat16* Vs = Ks + 2 * KT * SPAD;      // 2 buffers

    int tid  = threadIdx.x;
    int warp = tid >> 5;
    int lane = tid & 31;
    int gid  = lane >> 2;
    int l4   = lane & 3;
    int lrow = lane & 7;
    int lmat = lane >> 3;
    int i0 = blockIdx.x * QT;
    int h  = blockIdx.y;
    int b  = blockIdx.z;
    int g  = h >> 2;
    int wrow = warp * 16;

    // stage Q tile 64x128 bf16
    {
        int r = tid >> 1;
        int c = (tid & 1) * 64;
        const uint4* src = (const uint4*)(q + (((size_t)b * S_ + i0 + r) * HQ_ + h) * HD_ + c);
        uint4* dst = (uint4*)&Qs[r * SPAD + c];
#pragma unroll
        for (int u = 0; u < 8; u++) dst[u] = src[u];
    }
    __syncthreads();

    // Q fragments: 8 k-steps x 4 regs
    uint32_t qsb = smem_u32(Qs);
    uint32_t a_q[8][4];
#pragma unroll
    for (int ks = 0; ks < 8; ks++) {
        int mrow = wrow + (lmat & 1) * 8 + lrow;
        int mcol = ks * 16 + (lmat >> 1) * 8;
        uint32_t ad = qsb + 2u * (mrow * SPAD + mcol);
        asm volatile("ldmatrix.sync.aligned.m8n8.x4.shared.b16 {%0,%1,%2,%3}, [%4];"
                     : "=r"(a_q[ks][0]), "=r"(a_q[ks][1]),
                       "=r"(a_q[ks][2]), "=r"(a_q[ks][3]) : "r"(ad));
    }

    uint32_t ksb = smem_u32(Ks);
    uint32_t vsb = smem_u32(Vs);

    float m0 = -1e30f, m1 = -1e30f, l0 = 0.f, l1 = 0.f;
    float oa[16][4];
#pragma unroll
    for (int nt = 0; nt < 16; nt++)
#pragma unroll
        for (int r = 0; r < 4; r++) oa[nt][r] = 0.f;

    int irow0 = i0 + wrow + gid;
    int irow1 = irow0 + 8;
    int iwmax = i0 + wrow + 15;
    int iwmin = i0 + wrow;

    int jstart = max(0, i0 - (WINDOW_ - 1)) & ~(KT - 1);
    int iend   = i0 + QT - 1;
    const float scale = 0.08838834764831845f;

    const __nv_bfloat16* kb = k + (size_t)b * S_ * HKV_ * HD_ + g * HD_;
    const __nv_bfloat16* vb = v + (size_t)b * S_ * HKV_ * HD_ + g * HD_;

    // staging coords: 128 threads cover 32 rows x 128 cols (64B each)
    int sr = tid >> 2;
    int sc = (tid & 3) * 32;
    uint32_t kdst0 = ksb + 2u * (sr * SPAD + sc);
    uint32_t vdst0 = vsb + 2u * (sr * SPAD + sc);
    const uint32_t KVBUF = KT * SPAD * 2;   // bytes per buffer

    // prologue: stage first tile into buffer 0
    {
        size_t off = (size_t)(jstart + sr) * (HKV_ * HD_) + sc;
        const __nv_bfloat16* srk = kb + off;
        const __nv_bfloat16* srv = vb + off;
#pragma unroll
        for (int u = 0; u < 4; u++) {
            CP_ASYNC16(kdst0 + 16 * u, srk + 8 * u);
            CP_ASYNC16(vdst0 + 16 * u, srv + 8 * u);
        }
    }
    CP_COMMIT();

    int bufi = 0;
    for (int t0 = jstart; t0 <= iend; t0 += KT, bufi ^= 1) {
        int t1 = t0 + KT;
        if (t1 <= iend) {
            uint32_t bo = (bufi ^ 1) * KVBUF;
            size_t off = (size_t)(t1 + sr) * (HKV_ * HD_) + sc;
            const __nv_bfloat16* srk = kb + off;
            const __nv_bfloat16* srv = vb + off;
#pragma unroll
            for (int u = 0; u < 4; u++) {
                CP_ASYNC16(kdst0 + bo + 16 * u, srk + 8 * u);
                CP_ASYNC16(vdst0 + bo + 16 * u, srv + 8 * u);
            }
        }
        CP_COMMIT();
        CP_WAIT1();
        __syncthreads();

        uint32_t kbase = ksb + bufi * KVBUF;
        uint32_t vbase = vsb + bufi * KVBUF;

        bool live = (t0 <= iwmax) && (t0 + KT - 1 > iwmin - WINDOW_);
        if (live) {
            // ---- S = Q K^T ----
            float s[4][4];
#pragma unroll
            for (int nt = 0; nt < 4; nt++)
#pragma unroll
                for (int r = 0; r < 4; r++) s[nt][r] = 0.f;

#pragma unroll
            for (int ks = 0; ks < 8; ks++) {
                uint32_t b0[4], b1[4];
#pragma unroll
                for (int p = 0; p < 2; p++) {
                    int mrow = p * 16 + (lmat & 1) * 8 + lrow;
                    int mcol = ks * 16 + (lmat >> 1) * 8;
                    uint32_t ad = kbase + 2u * (mrow * SPAD + mcol);
                    uint32_t r0, r1, r2, r3;
                    asm volatile("ldmatrix.sync.aligned.m8n8.x4.shared.b16 {%0,%1,%2,%3}, [%4];"
                                 : "=r"(r0), "=r"(r1), "=r"(r2), "=r"(r3) : "r"(ad));
                    b0[2 * p] = r0; b0[2 * p + 1] = r1;
                    b1[2 * p] = r2; b1[2 * p + 1] = r3;
                }
#pragma unroll
                for (int nt = 0; nt < 4; nt++) {
                    asm volatile(
                        "mma.sync.aligned.m16n8k16.row.col.f32.bf16.bf16.f32 "
                        "{%0,%1,%2,%3}, {%4,%5,%6,%7}, {%8,%9}, {%0,%1,%2,%3};"
                        : "+f"(s[nt][0]), "+f"(s[nt][1]),
                          "+f"(s[nt][2]), "+f"(s[nt][3])
                        : "r"(a_q[ks][0]), "r"(a_q[ks][1]),
                          "r"(a_q[ks][2]), "r"(a_q[ks][3]),
                          "r"(b0[nt]), "r"(b1[nt]));
                }
            }

            // ---- scale + tanh cap + mask + online softmax ----
            float mx0 = -1e30f, mx1 = -1e30f;
#pragma unroll
            for (int nt = 0; nt < 4; nt++) {
                int j0 = t0 + nt * 8 + 2 * l4;
#pragma unroll
                for (int e = 0; e < 4; e++) {
                    int jj = j0 + (e & 1);
                    int ii = (e < 2) ? irow0 : irow1;
                    float x = s[nt][e] * scale;
                    float e2 = __expf(x * (-2.0f / CAP_));
                    x = CAP_ * __fdividef(1.f - e2, 1.f + e2);
                    bool valid = (jj <= ii) && (jj > ii - WINDOW_);
                    x = valid ? x : -1e30f;
                    s[nt][e] = x;
                    if (e < 2) mx0 = fmaxf(mx0, x);
                    else       mx1 = fmaxf(mx1, x);
                }
            }
            mx0 = fmaxf(mx0, __shfl_xor_sync(0xffffffffu, mx0, 1));
            mx0 = fmaxf(mx0, __shfl_xor_sync(0xffffffffu, mx0, 2));
            mx1 = fmaxf(mx1, __shfl_xor_sync(0xffffffffu, mx1, 1));
            mx1 = fmaxf(mx1, __shfl_xor_sync(0xffffffffu, mx1, 2));

            float mn0 = fmaxf(m0, mx0), mn1 = fmaxf(m1, mx1);
            float c0 = __expf(m0 - mn0), c1 = __expf(m1 - mn1);
            m0 = mn0; m1 = mn1;

            float rs0 = 0.f, rs1 = 0.f;
#pragma unroll
            for (int nt = 0; nt < 4; nt++) {
#pragma unroll
                for (int e = 0; e < 4; e++) {
                    float p = __expf(s[nt][e] - ((e < 2) ? mn0 : mn1));
                    s[nt][e] = p;
                    if (e < 2) rs0 += p; else rs1 += p;
                }
            }
            rs0 += __shfl_xor_sync(0xffffffffu, rs0, 1);
            rs0 += __shfl_xor_sync(0xffffffffu, rs0, 2);
            rs1 += __shfl_xor_sync(0xffffffffu, rs1, 1);
            rs1 += __shfl_xor_sync(0xffffffffu, rs1, 2);
            l0 = l0 * c0 + rs0;
            l1 = l1 * c1 + rs1;

#pragma unroll
            for (int nt = 0; nt < 16; nt++) {
                oa[nt][0] *= c0; oa[nt][1] *= c0;
                oa[nt][2] *= c1; oa[nt][3] *= c1;
            }

            uint32_t ap[2][4];
#pragma unroll
            for (int kp = 0; kp < 2; kp++) {
                int nA = 2 * kp, nB = 2 * kp + 1;
                ap[kp][0] = packbf(s[nA][0], s[nA][1]);
                ap[kp][1] = packbf(s[nA][2], s[nA][3]);
                ap[kp][2] = packbf(s[nB][0], s[nB][1]);
                ap[kp][3] = packbf(s[nB][2], s[nB][3]);
            }

            // ---- O += P V ----
#pragma unroll
            for (int kp = 0; kp < 2; kp++) {
#pragma unroll
                for (int ndp = 0; ndp < 8; ndp++) {
                    int mrow = kp * 16 + (lmat & 1) * 8 + lrow;
                    int mcol = ndp * 16 + (lmat >> 1) * 8;
                    uint32_t ad = vbase + 2u * (mrow * SPAD + mcol);
                    uint32_t r0, r1, r2, r3;
                    asm volatile("ldmatrix.sync.aligned.m8n8.x4.trans.shared.b16 {%0,%1,%2,%3}, [%4];"
                                 : "=r"(r0), "=r"(r1), "=r"(r2), "=r"(r3) : "r"(ad));
                    asm volatile(
                        "mma.sync.aligned.m16n8k16.row.col.f32.bf16.bf16.f32 "
                        "{%0,%1,%2,%3}, {%4,%5,%6,%7}, {%8,%9}, {%0,%1,%2,%3};"
                        : "+f"(oa[2 * ndp][0]), "+f"(oa[2 * ndp][1]),
                          "+f"(oa[2 * ndp][2]), "+f"(oa[2 * ndp][3])
                        : "r"(ap[kp][0]), "r"(ap[kp][1]),
                          "r"(ap[kp][2]), "r"(ap[kp][3]),
                          "r"(r0), "r"(r1));
                    asm volatile(
                        "mma.sync.aligned.m16n8k16.row.col.f32.bf16.bf16.f32 "
                        "{%0,%1,%2,%3}, {%4,%5,%6,%7}, {%8,%9}, {%0,%1,%2,%3};"
                        : "+f"(oa[2 * ndp + 1][0]), "+f"(oa[2 * ndp + 1][1]),
                          "+f"(oa[2 * ndp + 1][2]), "+f"(oa[2 * ndp + 1][3])
                        : "r"(ap[kp][0]), "r"(ap[kp][1]),
                          "r"(ap[kp][2]), "r"(ap[kp][3]),
                          "r"(r2), "r"(r3));
                }
            }
        }
        __syncthreads();
    }

    // epilogue
    float inv0 = 1.0f / l0;
    float inv1 = 1.0f / l1;
    __nv_bfloat16* ob0 = o + (((size_t)b * S_ + irow0) * HQ_ + h) * HD_;
    __nv_bfloat16* ob1 = o + (((size_t)b * S_ + irow1) * HQ_ + h) * HD_;
#pragma unroll
    for (int nt = 0; nt < 16; nt++) {
        int col = nt * 8 + 2 * l4;
        *(uint32_t*)(ob0 + col) = packbf(oa[nt][0] * inv0, oa[nt][1] * inv0);
        *(uint32_t*)(ob1 + col) = packbf(oa[nt][2] * inv1, oa[nt][3] * inv1);
    }
}

// ---------------- launch ----------------
extern "C" void kernel_launch(void* const* d_in, const int* in_sizes, int n_in,
                              void* d_out, int out_size) {
    const float* x     = (const float*)d_in[0];
    const float* gamma = (const float*)d_in[1];
    const float* Wq    = (const float*)d_in[2];
    const float* Wk    = (const float*)d_in[3];
    const float* Wv    = (const float*)d_in[4];
    const float* Wo    = (const float*)d_in[5];
    float* out = (float*)d_out;

    __nv_bfloat16 *xn, *ao, *wq16, *wk16, *wv16, *wo16, *q16, *k16, *v16;
    cudaGetSymbolAddress((void**)&xn, g_xn);
    cudaGetSymbolAddress((void**)&q16, g_q16);
    cudaGetSymbolAddress((void**)&k16, g_k16);
    cudaGetSymbolAddress((void**)&v16, g_v16);
    cudaGetSymbolAddress((void**)&ao, g_ao);
    cudaGetSymbolAddress((void**)&wq16, g_wq16);
    cudaGetSymbolAddress((void**)&wk16, g_wk16);
    cudaGetSymbolAddress((void**)&wv16, g_wv16);
    cudaGetSymbolAddress((void**)&wo16, g_wo16);

    cudaFuncSetAttribute(attn_mma_kernel,
                         cudaFuncAttributeMaxDynamicSharedMemorySize,
                         ATTN_SMEM_BYTES);

    // 0) weight conversion fp32 -> bf16
    {
        int n4q = HIDDEN_ * HQ_ * HD_ / 4;
        int n4k = HIDDEN_ * HKV_ * HD_ / 4;
        f2bf_kernel<<<(n4q + 255) / 256, 256>>>((const float4*)Wq, (__nv_bfloat162*)wq16, n4q);
        f2bf_kernel<<<(n4k + 255) / 256, 256>>>((const float4*)Wk, (__nv_bfloat162*)wk16, n4k);
        f2bf_kernel<<<(n4k + 255) / 256, 256>>>((const float4*)Wv, (__nv_bfloat162*)wv16, n4k);
        f2bf_kernel<<<(n4q + 255) / 256, 256>>>((const float4*)Wo, (__nv_bfloat162*)wo16, n4q);
    }

    // 1) RMSNorm (bf16 out)
    rmsnorm_kernel<<<M_ROWS, 256>>>(x, gamma, xn);

    // 2) Q/K/V projections -> bf16 directly
    dim3 gq(HQ_ * HD_ / TBN, M_ROWS / TBM);
    bf16_gemm_kernel<1><<<gq, 256>>>(xn, wq16, nullptr, q16, HQ_ * HD_, HIDDEN_);
    dim3 gk(HKV_ * HD_ / TBN, M_ROWS / TBM);
    bf16_gemm_kernel<1><<<gk, 256>>>(xn, wk16, nullptr, k16, HKV_ * HD_, HIDDEN_);
    bf16_gemm_kernel<1><<<gk, 256>>>(xn, wv16, nullptr, v16, HKV_ * HD_, HIDDEN_);

    // 3) RoPE in-place on bf16 q, k
    int tot_q = B_ * S_ * HQ_ * (HD_ / 2);
    rope_bf16_inplace<<<(tot_q + 255) / 256, 256>>>(q16, HQ_, tot_q);
    int tot_k = B_ * S_ * HKV_ * (HD_ / 2);
    rope_bf16_inplace<<<(tot_k + 255) / 256, 256>>>(k16, HKV_, tot_k);

    // 4) tensor-core flash attention (cp.async K/V pipeline)
    dim3 ga(S_ / QT, HQ_, B_);
    attn_mma_kernel<<<ga, 128, ATTN_SMEM_BYTES>>>(q16, k16, v16, ao);

    // 5) output projection + fp32 residual
    dim3 go(HIDDEN_ / TBN, M_ROWS / TBM);
    bf16_gemm_kernel<0><<<go, 256>>>(ao, wo16, x, out, HIDDEN_, HQ_ * HD_);
}